// round 4
// baseline (speedup 1.0000x reference)
#include <cuda_runtime.h>

// Problem constants
#define YY 5
#define NN 200000
#define GG 128
#define II 128
#define RR 3
#define BB 1024
#define KK 64
#define KTOT (RR * GG)   // 384

// Scratch (no cudaMalloc allowed)
__device__ float g_mean[(size_t)YY * BB * KTOT];   // A matrix: [y*B+b][r*G+g]

// ---------------------------------------------------------------------------
// Gather + masked mean: one CTA per (y, r, b).
// Warp w handles neighbor slots k = w, w+4, w+8, ...; lane owns g-columns
// lane*4..lane*4+3 (float4 loads). Cross-warp reduce through smem.
// int64-vs-int32 detection is done per-CTA from the first 64 words of counts
// (broadcast load): if all odd 32-bit words are zero, data is int64.
// ---------------------------------------------------------------------------
__global__ void __launch_bounds__(128) gather_mean_kernel(
        const float* __restrict__ emb,
        const void* __restrict__ nbr,
        const void* __restrict__ cnt) {
    const int b = blockIdx.x;
    const int r = blockIdx.y;
    const int y = blockIdx.z;
    const int tid  = threadIdx.x;
    const int w    = tid >> 5;
    const int lane = tid & 31;

    __shared__ int   s_is64;
    __shared__ int   s_cnt;
    __shared__ __align__(16) int   sidx[KK];
    __shared__ __align__(16) float part[4][GG];

    // dtype detection (warp 0): odd words of first 32 int64 candidates
    if (w == 0) {
        unsigned int v = ((const unsigned int*)cnt)[2 * lane + 1];
        unsigned int m = __ballot_sync(0xffffffffu, v != 0u);
        if (lane == 0) s_is64 = (m == 0u) ? 1 : 0;
    }
    __syncthreads();
    const int is64 = s_is64;

    const long long lin = ((long long)y * RR + r) * BB + b;
    if (tid == 0) {
        s_cnt = is64 ? (int)((const long long*)cnt)[lin]
                     : ((const int*)cnt)[lin];
    }
    if (tid < KK) {
        sidx[tid] = is64 ? (int)((const long long*)nbr)[lin * KK + tid]
                         : ((const int*)nbr)[lin * KK + tid];
    }
    __syncthreads();
    const int count = s_cnt;

    // float4 view of this year's embedding slab; row stride = 32 float4s
    const float4* e = (const float4*)(emb + (size_t)y * NN * GG) + lane;

    float4 acc = make_float4(0.f, 0.f, 0.f, 0.f);
    int k = w;
    for (; k + 4 < count; k += 8) {
        float4 v0 = e[(size_t)sidx[k] * 32];
        float4 v1 = e[(size_t)sidx[k + 4] * 32];
        acc.x += v0.x + v1.x;
        acc.y += v0.y + v1.y;
        acc.z += v0.z + v1.z;
        acc.w += v0.w + v1.w;
    }
    if (k < count) {
        float4 v0 = e[(size_t)sidx[k] * 32];
        acc.x += v0.x; acc.y += v0.y; acc.z += v0.z; acc.w += v0.w;
    }

    *(float4*)&part[w][lane * 4] = acc;
    __syncthreads();

    const float inv = 1.0f / (float)(count > 0 ? count : 1);
    float s = part[0][tid] + part[1][tid] + part[2][tid] + part[3][tid];
    g_mean[((size_t)y * BB + b) * KTOT + r * GG + tid] = s * inv;
}

// ---------------------------------------------------------------------------
// SGEMM: out[5120, 128] = g_mean[5120, 384] @ Weff[384, 128]
// Weff is built on the fly during staging:
//   k <  128 : Weff[k][i] = sum_c Wcite[c][k][i]
//   k >= 128 : Weff[k][i] = Wrel[k][i]        (same linear index)
// 256 threads (8 warps), BM=32 x BN=128, BK=32, grid=160.
// Warp w: rows (w&3)*8..+7, cols (w>>2)*64 + lane*2 (2 cols).
// f32x2-packed accumulators over row pairs; double-buffered smem.
// ---------------------------------------------------------------------------
#define BM 32
#define BN 128
#define BK 32
#define NCHUNK (KTOT / BK)   // 12
#define APAD 8               // A row stride 40 floats -> 16B aligned

__device__ __forceinline__ unsigned long long fma2(unsigned long long a,
                                                   unsigned long long b,
                                                   unsigned long long c) {
    unsigned long long d;
    asm("fma.rn.f32x2 %0, %1, %2, %3;" : "=l"(d) : "l"(a), "l"(b), "l"(c));
    return d;
}
__device__ __forceinline__ unsigned long long dup2(float x) {
    unsigned long long d;
    unsigned int u = __float_as_uint(x);
    asm("mov.b64 %0, {%1, %1};" : "=l"(d) : "r"(u));
    return d;
}
__device__ __forceinline__ float2 unpk2(unsigned long long p) {
    unsigned int lo, hi;
    asm("mov.b64 {%0, %1}, %2;" : "=r"(lo), "=r"(hi) : "l"(p));
    return make_float2(__uint_as_float(lo), __uint_as_float(hi));
}

__device__ __forceinline__ float4 weff_load(const float* __restrict__ Wrel,
                                            const float* __restrict__ Wcite,
                                            int k, int col4) {
    int idx = k * II + col4;
    if (k < GG) {
        float4 a = *(const float4*)(Wcite + idx);
        float4 b = *(const float4*)(Wcite + GG * II + idx);
        float4 c = *(const float4*)(Wcite + 2 * GG * II + idx);
        return make_float4(a.x + b.x + c.x, a.y + b.y + c.y,
                           a.z + b.z + c.z, a.w + b.w + c.w);
    }
    return *(const float4*)(Wrel + idx);
}

__global__ void __launch_bounds__(256) gemm_kernel(
        float* __restrict__ out,
        const float* __restrict__ Wrel,
        const float* __restrict__ Wcite) {
    __shared__ __align__(16) float Ast[2][BK][BM + APAD];  // transposed A
    __shared__ __align__(16) float Ws[2][BK][BN];

    const int tid  = threadIdx.x;        // 0..255
    const int w    = tid >> 5;           // warp 0..7
    const int rg   = w & 3;              // row group: rows rg*8..rg*8+7
    const int cg   = w >> 2;             // col half: cols cg*64..cg*64+63
    const int lane = tid & 31;           // cols cg*64 + lane*2 (+0,+1)
    const int rowbase = blockIdx.x * BM;

    unsigned long long acc[4][2];        // [rowpair][col]
    #pragma unroll
    for (int i = 0; i < 4; ++i) { acc[i][0] = 0ull; acc[i][1] = 0ull; }

    const float* Ag = g_mean + (size_t)rowbase * KTOT;

    // staging maps (256 threads)
    const int arow = tid >> 3;           // 0..31
    const int acol = (tid & 7) << 2;     // 0,4,...,28

    float4 pa;
    float4 pw[4];

    // prologue: load + stage chunk 0
    pa = *(const float4*)(Ag + (size_t)arow * KTOT + acol);
    #pragma unroll
    for (int j = 0; j < 4; ++j) {
        int l = tid + j * 256;
        pw[j] = weff_load(Wrel, Wcite, l >> 5, (l & 31) << 2);
    }
    Ast[0][acol + 0][arow] = pa.x;
    Ast[0][acol + 1][arow] = pa.y;
    Ast[0][acol + 2][arow] = pa.z;
    Ast[0][acol + 3][arow] = pa.w;
    #pragma unroll
    for (int j = 0; j < 4; ++j) {
        int l = tid + j * 256;
        *(float4*)&Ws[0][l >> 5][(l & 31) << 2] = pw[j];
    }
    __syncthreads();

    for (int c = 0; c < NCHUNK; ++c) {
        const int buf = c & 1;
        const bool more = (c + 1 < NCHUNK);
        if (more) {
            const int k0 = (c + 1) * BK;
            pa = *(const float4*)(Ag + (size_t)arow * KTOT + k0 + acol);
            #pragma unroll
            for (int j = 0; j < 4; ++j) {
                int l = tid + j * 256;
                pw[j] = weff_load(Wrel, Wcite, k0 + (l >> 5), (l & 31) << 2);
            }
        }

        #pragma unroll
        for (int kk = 0; kk < BK; ++kk) {
            ulonglong2 aP0 = *(const ulonglong2*)&Ast[buf][kk][rg * 8];      // rows 0-3
            ulonglong2 aP1 = *(const ulonglong2*)&Ast[buf][kk][rg * 8 + 4];  // rows 4-7
            float2 w2 = *(const float2*)&Ws[buf][kk][cg * 64 + lane * 2];
            unsigned long long wd0 = dup2(w2.x), wd1 = dup2(w2.y);

            acc[0][0] = fma2(aP0.x, wd0, acc[0][0]);
            acc[0][1] = fma2(aP0.x, wd1, acc[0][1]);
            acc[1][0] = fma2(aP0.y, wd0, acc[1][0]);
            acc[1][1] = fma2(aP0.y, wd1, acc[1][1]);
            acc[2][0] = fma2(aP1.x, wd0, acc[2][0]);
            acc[2][1] = fma2(aP1.x, wd1, acc[2][1]);
            acc[3][0] = fma2(aP1.y, wd0, acc[3][0]);
            acc[3][1] = fma2(aP1.y, wd1, acc[3][1]);
        }

        if (more) {
            const int nbuf = buf ^ 1;
            Ast[nbuf][acol + 0][arow] = pa.x;
            Ast[nbuf][acol + 1][arow] = pa.y;
            Ast[nbuf][acol + 2][arow] = pa.z;
            Ast[nbuf][acol + 3][arow] = pa.w;
            #pragma unroll
            for (int j = 0; j < 4; ++j) {
                int l = tid + j * 256;
                *(float4*)&Ws[nbuf][l >> 5][(l & 31) << 2] = pw[j];
            }
            __syncthreads();
        }
    }

    // epilogue: unpack row pairs, write float2 per row
    const int row0 = rowbase + rg * 8;
    float* o = out + (size_t)row0 * BN + cg * 64 + lane * 2;
    #pragma unroll
    for (int rp = 0; rp < 4; ++rp) {
        float2 c0 = unpk2(acc[rp][0]);   // col 0, rows (2rp, 2rp+1)
        float2 c1 = unpk2(acc[rp][1]);   // col 1
        *(float2*)(o + (size_t)(2 * rp) * BN)     = make_float2(c0.x, c1.x);
        *(float2*)(o + (size_t)(2 * rp + 1) * BN) = make_float2(c0.y, c1.y);
    }
}

// ---------------------------------------------------------------------------
// kernel_launch: gather means -> GEMM (Weff folded into GEMM staging)
// ---------------------------------------------------------------------------
extern "C" void kernel_launch(void* const* d_in, const int* in_sizes, int n_in,
                              void* d_out, int out_size) {
    const float* emb   = (const float*)d_in[0];
    const float* Wrel  = (const float*)d_in[1];
    const float* Wcite = (const float*)d_in[2];
    const void*  nbr   = d_in[3];
    const void*  cnt   = d_in[4];
    float* out = (float*)d_out;

    dim3 g1(BB, RR, YY);   // z (year) slowest -> year locality in L2
    gather_mean_kernel<<<g1, 128>>>(emb, nbr, cnt);

    gemm_kernel<<<(YY * BB) / BM, 256>>>(out, Wrel, Wcite);
}

// round 5
// speedup vs baseline: 1.1071x; 1.1071x over previous
#include <cuda_runtime.h>

// Problem constants
#define YY 5
#define NN 200000
#define GG 128
#define II 128
#define RR 3
#define BB 1024
#define KK 64
#define KTOT (RR * GG)   // 384

#define NWEFF_BLK 192    // weff-builder CTAs prepended to gather grid

// Scratch (no cudaMalloc allowed)
__device__ float g_mean[(size_t)YY * BB * KTOT];   // A matrix: [y*B+b][r*G+g]
__device__ float g_weff[KTOT * II];                // Weff:     [r*G+g][i]

// ---------------------------------------------------------------------------
// Fused kernel #1 (flattened 1D grid, 128 threads):
//   blocks [0, 192):        build g_weff (Weff[0]=sum Wcite; Weff[1..2]=Wrel)
//   blocks [192, 192+15360): gather + masked mean, one CTA per (y, r, b)
// Gather: warp w handles neighbor slots k = w, w+4, ...; lane owns g-columns
// lane*4..+3 (float4). Cross-warp reduce through smem.
// int64-vs-int32 detection per-CTA from first 64 words of counts (broadcast).
// ---------------------------------------------------------------------------
__global__ void __launch_bounds__(128) gather_mean_kernel(
        const float* __restrict__ emb,
        const void* __restrict__ nbr,
        const void* __restrict__ cnt,
        const float* __restrict__ Wrel,
        const float* __restrict__ Wcite) {
    const int bid = blockIdx.x;
    const int tid  = threadIdx.x;

    if (bid < NWEFF_BLK) {
        // Weff build: 49152 elems, 2 per thread
        #pragma unroll
        for (int j = 0; j < 2; ++j) {
            int idx = bid * 256 + j * 128 + tid;
            int r  = idx / (GG * II);
            int gi = idx - r * (GG * II);
            float v;
            if (r == 0)
                v = Wcite[gi] + Wcite[GG * II + gi] + Wcite[2 * GG * II + gi];
            else
                v = Wrel[idx];
            g_weff[idx] = v;
        }
        return;
    }

    const int gid = bid - NWEFF_BLK;
    const int y   = gid / (RR * BB);
    const int rem = gid - y * (RR * BB);
    const int r   = rem >> 10;
    const int b   = rem & (BB - 1);
    const int w    = tid >> 5;
    const int lane = tid & 31;

    __shared__ int   s_is64;
    __shared__ int   s_cnt;
    __shared__ __align__(16) int   sidx[KK];
    __shared__ __align__(16) float part[4][GG];

    // dtype detection (warp 0): odd words of first 32 int64 candidates
    if (w == 0) {
        unsigned int v = ((const unsigned int*)cnt)[2 * lane + 1];
        unsigned int m = __ballot_sync(0xffffffffu, v != 0u);
        if (lane == 0) s_is64 = (m == 0u) ? 1 : 0;
    }
    __syncthreads();
    const int is64 = s_is64;

    const long long lin = ((long long)y * RR + r) * BB + b;
    if (tid == 0) {
        s_cnt = is64 ? (int)((const long long*)cnt)[lin]
                     : ((const int*)cnt)[lin];
    }
    if (tid < KK) {
        sidx[tid] = is64 ? (int)((const long long*)nbr)[lin * KK + tid]
                         : ((const int*)nbr)[lin * KK + tid];
    }
    __syncthreads();
    const int count = s_cnt;

    // float4 view of this year's embedding slab; row stride = 32 float4s
    const float4* e = (const float4*)(emb + (size_t)y * NN * GG) + lane;

    float4 acc = make_float4(0.f, 0.f, 0.f, 0.f);
    int k = w;
    for (; k + 4 < count; k += 8) {
        float4 v0 = e[(size_t)sidx[k] * 32];
        float4 v1 = e[(size_t)sidx[k + 4] * 32];
        acc.x += v0.x + v1.x;
        acc.y += v0.y + v1.y;
        acc.z += v0.z + v1.z;
        acc.w += v0.w + v1.w;
    }
    if (k < count) {
        float4 v0 = e[(size_t)sidx[k] * 32];
        acc.x += v0.x; acc.y += v0.y; acc.z += v0.z; acc.w += v0.w;
    }

    *(float4*)&part[w][lane * 4] = acc;
    __syncthreads();

    const float inv = 1.0f / (float)(count > 0 ? count : 1);
    float s = part[0][tid] + part[1][tid] + part[2][tid] + part[3][tid];
    g_mean[((size_t)y * BB + b) * KTOT + r * GG + tid] = s * inv;
}

// ---------------------------------------------------------------------------
// SGEMM: out[5120, 128] = g_mean[5120, 384] @ g_weff[384, 128]
// 256 threads (8 warps), BM=32 x BN=128, BK=32, grid=160.
// Warp w: rows (w&3)*8..+7, cols (w>>2)*64 + lane*2.
// f32x2-packed accumulators over row pairs; double-buffered smem;
// W staged with plain float4 loads (short dependency chain).
// ---------------------------------------------------------------------------
#define BM 32
#define BN 128
#define BK 32
#define NCHUNK (KTOT / BK)   // 12
#define APAD 8               // A row stride 40 floats -> 16B aligned

__device__ __forceinline__ unsigned long long fma2(unsigned long long a,
                                                   unsigned long long b,
                                                   unsigned long long c) {
    unsigned long long d;
    asm("fma.rn.f32x2 %0, %1, %2, %3;" : "=l"(d) : "l"(a), "l"(b), "l"(c));
    return d;
}
__device__ __forceinline__ unsigned long long dup2(float x) {
    unsigned long long d;
    unsigned int u = __float_as_uint(x);
    asm("mov.b64 %0, {%1, %1};" : "=l"(d) : "r"(u));
    return d;
}
__device__ __forceinline__ float2 unpk2(unsigned long long p) {
    unsigned int lo, hi;
    asm("mov.b64 {%0, %1}, %2;" : "=r"(lo), "=r"(hi) : "l"(p));
    return make_float2(__uint_as_float(lo), __uint_as_float(hi));
}

__global__ void __launch_bounds__(256) gemm_kernel(float* __restrict__ out) {
    __shared__ __align__(16) float Ast[2][BK][BM + APAD];  // transposed A
    __shared__ __align__(16) float Ws[2][BK][BN];

    const int tid  = threadIdx.x;        // 0..255
    const int w    = tid >> 5;           // warp 0..7
    const int rg   = w & 3;              // rows rg*8..rg*8+7
    const int cg   = w >> 2;             // cols cg*64..cg*64+63
    const int lane = tid & 31;           // cols cg*64 + lane*2 (+0,+1)
    const int rowbase = blockIdx.x * BM;

    unsigned long long acc[4][2];        // [rowpair][col]
    #pragma unroll
    for (int i = 0; i < 4; ++i) { acc[i][0] = 0ull; acc[i][1] = 0ull; }

    const float* Ag = g_mean + (size_t)rowbase * KTOT;

    // staging maps (256 threads)
    const int arow = tid >> 3;           // 0..31
    const int acol = (tid & 7) << 2;     // 0,4,...,28
    const int wrow = tid >> 5;           // 0..7   (k within chunk, +8 per j)
    const int wcol = (tid & 31) << 2;    // 0..124

    float4 pa;
    float4 pw[4];

    // prologue: load + stage chunk 0
    pa = *(const float4*)(Ag + (size_t)arow * KTOT + acol);
    #pragma unroll
    for (int j = 0; j < 4; ++j)
        pw[j] = *(const float4*)(g_weff + (size_t)(wrow + j * 8) * BN + wcol);
    Ast[0][acol + 0][arow] = pa.x;
    Ast[0][acol + 1][arow] = pa.y;
    Ast[0][acol + 2][arow] = pa.z;
    Ast[0][acol + 3][arow] = pa.w;
    #pragma unroll
    for (int j = 0; j < 4; ++j)
        *(float4*)&Ws[0][wrow + j * 8][wcol] = pw[j];
    __syncthreads();

    for (int c = 0; c < NCHUNK; ++c) {
        const int buf = c & 1;
        const bool more = (c + 1 < NCHUNK);
        if (more) {
            const int k0 = (c + 1) * BK;
            pa = *(const float4*)(Ag + (size_t)arow * KTOT + k0 + acol);
            #pragma unroll
            for (int j = 0; j < 4; ++j)
                pw[j] = *(const float4*)(g_weff + (size_t)(k0 + wrow + j * 8) * BN + wcol);
        }

        #pragma unroll
        for (int kk = 0; kk < BK; ++kk) {
            ulonglong2 aP0 = *(const ulonglong2*)&Ast[buf][kk][rg * 8];      // rows 0-3
            ulonglong2 aP1 = *(const ulonglong2*)&Ast[buf][kk][rg * 8 + 4];  // rows 4-7
            float2 w2 = *(const float2*)&Ws[buf][kk][cg * 64 + lane * 2];
            unsigned long long wd0 = dup2(w2.x), wd1 = dup2(w2.y);

            acc[0][0] = fma2(aP0.x, wd0, acc[0][0]);
            acc[0][1] = fma2(aP0.x, wd1, acc[0][1]);
            acc[1][0] = fma2(aP0.y, wd0, acc[1][0]);
            acc[1][1] = fma2(aP0.y, wd1, acc[1][1]);
            acc[2][0] = fma2(aP1.x, wd0, acc[2][0]);
            acc[2][1] = fma2(aP1.x, wd1, acc[2][1]);
            acc[3][0] = fma2(aP1.y, wd0, acc[3][0]);
            acc[3][1] = fma2(aP1.y, wd1, acc[3][1]);
        }

        if (more) {
            const int nbuf = buf ^ 1;
            Ast[nbuf][acol + 0][arow] = pa.x;
            Ast[nbuf][acol + 1][arow] = pa.y;
            Ast[nbuf][acol + 2][arow] = pa.z;
            Ast[nbuf][acol + 3][arow] = pa.w;
            #pragma unroll
            for (int j = 0; j < 4; ++j)
                *(float4*)&Ws[nbuf][wrow + j * 8][wcol] = pw[j];
            __syncthreads();
        }
    }

    // epilogue: unpack row pairs, write float2 per row
    const int row0 = rowbase + rg * 8;
    float* o = out + (size_t)row0 * BN + cg * 64 + lane * 2;
    #pragma unroll
    for (int rp = 0; rp < 4; ++rp) {
        float2 c0 = unpk2(acc[rp][0]);   // col 0, rows (2rp, 2rp+1)
        float2 c1 = unpk2(acc[rp][1]);   // col 1
        *(float2*)(o + (size_t)(2 * rp) * BN)     = make_float2(c0.x, c1.x);
        *(float2*)(o + (size_t)(2 * rp + 1) * BN) = make_float2(c0.y, c1.y);
    }
}

// ---------------------------------------------------------------------------
// kernel_launch: [weff-build + gather] -> GEMM
// ---------------------------------------------------------------------------
extern "C" void kernel_launch(void* const* d_in, const int* in_sizes, int n_in,
                              void* d_out, int out_size) {
    const float* emb   = (const float*)d_in[0];
    const float* Wrel  = (const float*)d_in[1];
    const float* Wcite = (const float*)d_in[2];
    const void*  nbr   = d_in[3];
    const void*  cnt   = d_in[4];
    float* out = (float*)d_out;

    gather_mean_kernel<<<NWEFF_BLK + YY * RR * BB, 128>>>(emb, nbr, cnt, Wrel, Wcite);

    gemm_kernel<<<(YY * BB) / BM, 256>>>(out);
}